// round 3
// baseline (speedup 1.0000x reference)
#include <cuda_runtime.h>
#include <cstdint>

// CausalAttentionProduct — flash attention, tf32 mma.sync, pre-converted
// smem operands + permuted contraction dims for LDS.64 fragment loads.
// B=2, H=12, S=4096, D=64. BM=128, BN=64, 4 warps, 2 CTA/SM.
// Reference quirk: scores[..., -128:, -128:] OVERWRITTEN with (0 if k<=q else -inf).

#define NB 2
#define NH 12
#define S_LEN 4096
#define DH 64
#define BM 128
#define BN 64
#define NWARP 4
#define LOG2E 1.4426950408889634f
#define NEG_BIG (-1e30f)

// All tiles pitch 72 (72 mod 32 == 8): LDS.64 at (row*72 + 2*tg) with row
// varying by g gives banks (8g+2tg) -> conflict-free per half-warp.
#define PITCH 72
#define OFF_QS 0
#define OFF_KS (OFF_QS + BM * PITCH)            //  9216
#define OFF_VT (OFF_KS + BN * PITCH)            // 13824  Vt[d][n-slot]
#define OFF_PS (OFF_VT + DH * PITCH)            // 18432  per-warp 32x72
#define OFF_MK (OFF_PS + NWARP * 32 * PITCH)    // 27648
#define SMEM_FLOATS (OFF_MK + BN)               // 27712
#define SMEM_BYTES (SMEM_FLOATS * 4)            // 110848 B -> 2 CTA/SM

extern __shared__ float smem[];

__device__ __forceinline__ float f2tf(float x) {
    uint32_t r;
    asm("cvt.rna.tf32.f32 %0, %1;" : "=r"(r) : "f"(x));
    return __uint_as_float(r);
}
__device__ __forceinline__ float ex2(float x) {
    float r;
    asm("ex2.approx.ftz.f32 %0, %1;" : "=f"(r) : "f"(x));
    return r;
}
__device__ __forceinline__ void mma_tf32(float c[4],
                                         float a0, float a1, float a2, float a3,
                                         float b0, float b1) {
    asm volatile(
        "mma.sync.aligned.m16n8k8.row.col.f32.tf32.tf32.f32 "
        "{%0,%1,%2,%3}, {%4,%5,%6,%7}, {%8,%9}, {%0,%1,%2,%3};"
        : "+f"(c[0]), "+f"(c[1]), "+f"(c[2]), "+f"(c[3])
        : "r"(__float_as_uint(a0)), "r"(__float_as_uint(a1)),
          "r"(__float_as_uint(a2)), "r"(__float_as_uint(a3)),
          "r"(__float_as_uint(b0)), "r"(__float_as_uint(b1)));
}

// sigma(r): within-8-group permutation so slot pair (2t,2t+1) = logical (t, t+4)
__device__ __forceinline__ int sigma(int r) {
    return (r < 4) ? 2 * r : 2 * (r - 4) + 1;
}

__global__ void __launch_bounds__(128, 2)
attn_tf32_kernel(const float* __restrict__ Q,
                 const float* __restrict__ K,
                 const float* __restrict__ V,
                 const float* __restrict__ mask,
                 float* __restrict__ O)
{
    float* Qs = smem + OFF_QS;
    float* Ks = smem + OFF_KS;
    float* Vt = smem + OFF_VT;
    float* mk = smem + OFF_MK;

    const int tid  = threadIdx.x;
    const int warp = tid >> 5;
    const int lane = tid & 31;
    const int g    = lane >> 2;   // 0..7
    const int tg   = lane & 3;    // 0..3

    float* Ps = smem + OFF_PS + warp * 32 * PITCH;

    const int bh    = blockIdx.y;
    const int b     = bh / NH;
    const int qbase = blockIdx.x * BM;
    const bool qsp  = (qbase == S_LEN - BM);

    const float* Qp = Q + (size_t)bh * S_LEN * DH;
    const float* Kp = K + (size_t)bh * S_LEN * DH;
    const float* Vp = V + (size_t)bh * S_LEN * DH;
    const float* Mp = mask + (size_t)b * S_LEN;
    float* Op = O + (size_t)bh * S_LEN * DH;

    // P-store slot constants (permuted n within 8-group)
    const int ps0 = (tg < 2) ? 4 * tg : 4 * tg - 7;       // sigma(2tg)
    const int ps1 = (tg < 2) ? 4 * tg + 2 : 4 * tg - 5;   // sigma(2tg+1)

    // ---- load Q tile: scale, convert to tf32, permute d within 8-groups ----
    {
        const float qscale = 0.125f * LOG2E;
        const int r0 = tid >> 4;      // 0..7
        const int c4 = tid & 15;      // float4 index along D
        const int base = 8 * (c4 >> 1) + (c4 & 1);  // slot base, step 2
        #pragma unroll
        for (int i = 0; i < 16; i++) {
            int m = r0 + 8 * i;
            float4 v = *(const float4*)(Qp + (size_t)(qbase + m) * DH + c4 * 4);
            float* q = Qs + m * PITCH + base;
            q[0] = f2tf(v.x * qscale);
            q[2] = f2tf(v.y * qscale);
            q[4] = f2tf(v.z * qscale);
            q[6] = f2tf(v.w * qscale);
        }
    }

    float m_st[2][2], l_st[2][2];
    float oacc[2][8][4];
    #pragma unroll
    for (int at = 0; at < 2; at++)
        #pragma unroll
        for (int rh = 0; rh < 2; rh++) { m_st[at][rh] = NEG_BIG; l_st[at][rh] = 0.0f; }
    #pragma unroll
    for (int at = 0; at < 2; at++)
        #pragma unroll
        for (int nt = 0; nt < 8; nt++)
            #pragma unroll
            for (int j = 0; j < 4; j++) oacc[at][nt][j] = 0.0f;

    const int wrow = warp * 32;

    for (int kt = 0; kt < S_LEN / BN; kt++) {
        const int kbase = kt * BN;

        __syncthreads();

        // ---- stage K (d-permuted), V (transposed, n-permuted), mask ----
        {
            const int r0 = tid >> 4;
            const int c4 = tid & 15;
            const int base = 8 * (c4 >> 1) + (c4 & 1);
            #pragma unroll
            for (int i = 0; i < 8; i++) {
                int n = r0 + 8 * i;
                float4 kv = *(const float4*)(Kp + (size_t)(kbase + n) * DH + c4 * 4);
                float* k = Ks + n * PITCH + base;
                k[0] = f2tf(kv.x);
                k[2] = f2tf(kv.y);
                k[4] = f2tf(kv.z);
                k[6] = f2tf(kv.w);
            }
            // V: thread owns row n (fixed), a 32-wide d range; transpose into Vt[d][nslot]
            const int vn    = tid & 63;
            const int dbase = (tid >> 6) * 32;
            const int nslot = 8 * (vn >> 3) + sigma(vn & 7);
            const float* vrow = Vp + (size_t)(kbase + vn) * DH + dbase;
            #pragma unroll
            for (int i = 0; i < 8; i++) {
                float4 vv = *(const float4*)(vrow + 4 * i);
                int d = dbase + 4 * i;
                Vt[(d + 0) * PITCH + nslot] = f2tf(vv.x);
                Vt[(d + 1) * PITCH + nslot] = f2tf(vv.y);
                Vt[(d + 2) * PITCH + nslot] = f2tf(vv.z);
                Vt[(d + 3) * PITCH + nslot] = f2tf(vv.w);
            }
            if (tid < BN) mk[tid] = Mp[kbase + tid] * LOG2E;
        }
        __syncthreads();

        // ---- S = Q @ K^T ----
        float sacc[2][8][4];
        #pragma unroll
        for (int at = 0; at < 2; at++)
            #pragma unroll
            for (int nt = 0; nt < 8; nt++)
                #pragma unroll
                for (int j = 0; j < 4; j++) sacc[at][nt][j] = 0.0f;

        #pragma unroll
        for (int ks = 0; ks < 8; ks++) {
            float2 a02[2], a13[2];
            #pragma unroll
            for (int at = 0; at < 2; at++) {
                const float* qr = Qs + (wrow + at * 16 + g) * PITCH + ks * 8 + 2 * tg;
                a02[at] = *(const float2*)(qr);
                a13[at] = *(const float2*)(qr + 8 * PITCH);
            }
            #pragma unroll
            for (int nt = 0; nt < 8; nt++) {
                float2 b01 = *(const float2*)(Ks + (nt * 8 + g) * PITCH + ks * 8 + 2 * tg);
                mma_tf32(sacc[0][nt], a02[0].x, a13[0].x, a02[0].y, a13[0].y, b01.x, b01.y);
                mma_tf32(sacc[1][nt], a02[1].x, a13[1].x, a02[1].y, a13[1].y, b01.x, b01.y);
            }
        }

        // ---- mask add / special overwrite ----
        if (qsp && kbase >= S_LEN - 128) {
            #pragma unroll
            for (int at = 0; at < 2; at++)
                #pragma unroll
                for (int nt = 0; nt < 8; nt++)
                    #pragma unroll
                    for (int j = 0; j < 4; j++) {
                        int qg = qbase + wrow + at * 16 + g + (j >> 1) * 8;
                        int kg = kbase + nt * 8 + 2 * tg + (j & 1);
                        sacc[at][nt][j] = (kg <= qg) ? 0.0f : NEG_BIG;
                    }
        } else {
            #pragma unroll
            for (int nt = 0; nt < 8; nt++) {
                float2 mv = *(const float2*)(mk + nt * 8 + 2 * tg);
                #pragma unroll
                for (int at = 0; at < 2; at++) {
                    sacc[at][nt][0] += mv.x;
                    sacc[at][nt][1] += mv.y;
                    sacc[at][nt][2] += mv.x;
                    sacc[at][nt][3] += mv.y;
                }
            }
        }

        // ---- online softmax (exp2 domain) ----
        #pragma unroll
        for (int at = 0; at < 2; at++) {
            #pragma unroll
            for (int rh = 0; rh < 2; rh++) {
                float tm = NEG_BIG;
                #pragma unroll
                for (int nt = 0; nt < 8; nt++) {
                    tm = fmaxf(tm, sacc[at][nt][2 * rh]);
                    tm = fmaxf(tm, sacc[at][nt][2 * rh + 1]);
                }
                tm = fmaxf(tm, __shfl_xor_sync(0xffffffffu, tm, 1));
                tm = fmaxf(tm, __shfl_xor_sync(0xffffffffu, tm, 2));
                float mn = fmaxf(m_st[at][rh], tm);
                float corr = ex2(m_st[at][rh] - mn);
                m_st[at][rh] = mn;
                float ls = 0.0f;
                #pragma unroll
                for (int nt = 0; nt < 8; nt++) {
                    float p0 = ex2(sacc[at][nt][2 * rh] - mn);
                    float p1 = ex2(sacc[at][nt][2 * rh + 1] - mn);
                    sacc[at][nt][2 * rh] = p0;
                    sacc[at][nt][2 * rh + 1] = p1;
                    ls += p0 + p1;
                }
                ls += __shfl_xor_sync(0xffffffffu, ls, 1);
                ls += __shfl_xor_sync(0xffffffffu, ls, 2);
                l_st[at][rh] = l_st[at][rh] * corr + ls;
                #pragma unroll
                for (int nt = 0; nt < 8; nt++) {
                    oacc[at][nt][2 * rh] *= corr;
                    oacc[at][nt][2 * rh + 1] *= corr;
                }
            }
        }

        // ---- P -> smem, tf32-converted, n-permuted slots ----
        __syncwarp();
        #pragma unroll
        for (int at = 0; at < 2; at++)
            #pragma unroll
            for (int nt = 0; nt < 8; nt++)
                #pragma unroll
                for (int rh = 0; rh < 2; rh++) {
                    float* pr = Ps + (at * 16 + g + 8 * rh) * PITCH + nt * 8;
                    pr[ps0] = f2tf(sacc[at][nt][2 * rh]);
                    pr[ps1] = f2tf(sacc[at][nt][2 * rh + 1]);
                }
        __syncwarp();

        // ---- O += P @ V ----
        #pragma unroll
        for (int ks = 0; ks < 8; ks++) {
            float2 a02[2], a13[2];
            #pragma unroll
            for (int at = 0; at < 2; at++) {
                const float* pr = Ps + (at * 16 + g) * PITCH + ks * 8 + 2 * tg;
                a02[at] = *(const float2*)(pr);
                a13[at] = *(const float2*)(pr + 8 * PITCH);
            }
            #pragma unroll
            for (int nt = 0; nt < 8; nt++) {
                float2 b01 = *(const float2*)(Vt + (nt * 8 + g) * PITCH + ks * 8 + 2 * tg);
                mma_tf32(oacc[0][nt], a02[0].x, a13[0].x, a02[0].y, a13[0].y, b01.x, b01.y);
                mma_tf32(oacc[1][nt], a02[1].x, a13[1].x, a02[1].y, a13[1].y, b01.x, b01.y);
            }
        }
    }

    // ---- epilogue ----
    #pragma unroll
    for (int at = 0; at < 2; at++) {
        #pragma unroll
        for (int rh = 0; rh < 2; rh++) {
            float inv = 1.0f / l_st[at][rh];
            size_t row = (size_t)(qbase + wrow + at * 16 + g + 8 * rh);
            #pragma unroll
            for (int nt = 0; nt < 8; nt++) {
                float2 ov = make_float2(oacc[at][nt][2 * rh] * inv,
                                        oacc[at][nt][2 * rh + 1] * inv);
                *(float2*)(Op + row * DH + nt * 8 + 2 * tg) = ov;
            }
        }
    }
}

extern "C" void kernel_launch(void* const* d_in, const int* in_sizes, int n_in,
                              void* d_out, int out_size)
{
    (void)in_sizes; (void)n_in; (void)out_size;
    const float* Q    = (const float*)d_in[0];
    const float* K    = (const float*)d_in[1];
    const float* V    = (const float*)d_in[2];
    const float* mask = (const float*)d_in[3];
    float* O = (float*)d_out;

    cudaFuncSetAttribute(attn_tf32_kernel,
                         cudaFuncAttributeMaxDynamicSharedMemorySize, SMEM_BYTES);

    dim3 grid(S_LEN / BM, NB * NH);
    attn_tf32_kernel<<<grid, 128, SMEM_BYTES>>>(Q, K, V, mask, O);
}

// round 4
// speedup vs baseline: 1.5384x; 1.5384x over previous
#include <cuda_runtime.h>
#include <cstdint>

// CausalAttentionProduct — flash attention, tf32 mma.sync.
// R4: R2 memory patterns + staged tf32 pre-convert + in-register P exchange
// (quad shuffles) instead of smem round-trip -> 71KB smem -> 3 CTA/SM.
// B=2, H=12, S=4096, D=64. BM=128, BN=64, 4 warps.
// Reference quirk: scores[..., -128:, -128:] OVERWRITTEN with (0 if k<=q else -inf).

#define NB 2
#define NH 12
#define S_LEN 4096
#define DH 64
#define BM 128
#define BN 64
#define LOG2E 1.4426950408889634f
#define NEG_BIG (-1e30f)

#define QS_PITCH 68
#define KS_PITCH 68
#define VS_PITCH 72
#define OFF_QS 0
#define OFF_KS (OFF_QS + BM * QS_PITCH)          //  8704
#define OFF_VS (OFF_KS + BN * KS_PITCH)          // 13056
#define OFF_MK (OFF_VS + BN * VS_PITCH)          // 17664
#define SMEM_FLOATS (OFF_MK + BN)                // 17728
#define SMEM_BYTES (SMEM_FLOATS * 4)             // 70912 B -> 3 CTA/SM

extern __shared__ float smem[];

__device__ __forceinline__ float f2tf(float x) {
    uint32_t r;
    asm("cvt.rna.tf32.f32 %0, %1;" : "=r"(r) : "f"(x));
    return __uint_as_float(r);
}
__device__ __forceinline__ float ex2(float x) {
    float r;
    asm("ex2.approx.ftz.f32 %0, %1;" : "=f"(r) : "f"(x));
    return r;
}
__device__ __forceinline__ void mma_tf32(float c[4],
                                         float a0, float a1, float a2, float a3,
                                         float b0, float b1) {
    asm volatile(
        "mma.sync.aligned.m16n8k8.row.col.f32.tf32.tf32.f32 "
        "{%0,%1,%2,%3}, {%4,%5,%6,%7}, {%8,%9}, {%0,%1,%2,%3};"
        : "+f"(c[0]), "+f"(c[1]), "+f"(c[2]), "+f"(c[3])
        : "r"(__float_as_uint(a0)), "r"(__float_as_uint(a1)),
          "r"(__float_as_uint(a2)), "r"(__float_as_uint(a3)),
          "r"(__float_as_uint(b0)), "r"(__float_as_uint(b1)));
}

__global__ void __launch_bounds__(128, 3)
attn_tf32_kernel(const float* __restrict__ Q,
                 const float* __restrict__ K,
                 const float* __restrict__ V,
                 const float* __restrict__ mask,
                 float* __restrict__ O)
{
    float* Qs = smem + OFF_QS;
    float* Ks = smem + OFF_KS;
    float* Vs = smem + OFF_VS;
    float* mk = smem + OFF_MK;

    const int tid  = threadIdx.x;
    const int warp = tid >> 5;
    const int lane = tid & 31;
    const int g    = lane >> 2;   // 0..7
    const int tg   = lane & 3;    // 0..3

    const int bh    = blockIdx.y;
    const int b     = bh / NH;
    const int qbase = blockIdx.x * BM;
    const bool qsp  = (qbase == S_LEN - BM);

    const float* Qp = Q + (size_t)bh * S_LEN * DH;
    const float* Kp = K + (size_t)bh * S_LEN * DH;
    const float* Vp = V + (size_t)bh * S_LEN * DH;
    const float* Mp = mask + (size_t)b * S_LEN;
    float* Op = O + (size_t)bh * S_LEN * DH;

    // quad-shuffle source lanes for c->a fragment exchange
    const int qbl = (lane & 28) | (tg >> 1);   // base quad lane
    const bool podd = (tg & 1);

    // ---- load Q tile (scale folded, tf32 pre-converted) ----
    {
        const float qscale = 0.125f * LOG2E;
        const int r0 = tid >> 4;
        const int c4 = tid & 15;
        #pragma unroll
        for (int i = 0; i < 16; i++) {
            int m = r0 + 8 * i;
            float4 v = *(const float4*)(Qp + (size_t)(qbase + m) * DH + c4 * 4);
            float4 w = make_float4(f2tf(v.x * qscale), f2tf(v.y * qscale),
                                   f2tf(v.z * qscale), f2tf(v.w * qscale));
            *(float4*)(Qs + m * QS_PITCH + c4 * 4) = w;
        }
    }

    float m_st[2][2], l_st[2][2];
    float oacc[2][8][4];
    #pragma unroll
    for (int at = 0; at < 2; at++)
        #pragma unroll
        for (int rh = 0; rh < 2; rh++) { m_st[at][rh] = NEG_BIG; l_st[at][rh] = 0.0f; }
    #pragma unroll
    for (int at = 0; at < 2; at++)
        #pragma unroll
        for (int nt = 0; nt < 8; nt++)
            #pragma unroll
            for (int j = 0; j < 4; j++) oacc[at][nt][j] = 0.0f;

    const int wrow = warp * 32;

    for (int kt = 0; kt < S_LEN / BN; kt++) {
        const int kbase = kt * BN;

        __syncthreads();

        // ---- stage K, V (tf32 pre-converted) + mask chunk ----
        {
            const int r0 = tid >> 4;
            const int c4 = tid & 15;
            #pragma unroll
            for (int i = 0; i < 8; i++) {
                int n = r0 + 8 * i;
                float4 kv = *(const float4*)(Kp + (size_t)(kbase + n) * DH + c4 * 4);
                float4 kw = make_float4(f2tf(kv.x), f2tf(kv.y), f2tf(kv.z), f2tf(kv.w));
                *(float4*)(Ks + n * KS_PITCH + c4 * 4) = kw;
                float4 vv = *(const float4*)(Vp + (size_t)(kbase + n) * DH + c4 * 4);
                float4 vw = make_float4(f2tf(vv.x), f2tf(vv.y), f2tf(vv.z), f2tf(vv.w));
                *(float4*)(Vs + n * VS_PITCH + c4 * 4) = vw;
            }
            if (tid < BN) mk[tid] = Mp[kbase + tid] * LOG2E;
        }
        __syncthreads();

        // ---- S = Q @ K^T ----
        float sacc[2][8][4];
        #pragma unroll
        for (int at = 0; at < 2; at++)
            #pragma unroll
            for (int nt = 0; nt < 8; nt++)
                #pragma unroll
                for (int j = 0; j < 4; j++) sacc[at][nt][j] = 0.0f;

        #pragma unroll
        for (int ks = 0; ks < 8; ks++) {
            float a[2][4];
            #pragma unroll
            for (int at = 0; at < 2; at++) {
                const float* qr = Qs + (wrow + at * 16 + g) * QS_PITCH + ks * 8;
                a[at][0] = qr[tg];
                a[at][1] = qr[8 * QS_PITCH + tg];
                a[at][2] = qr[tg + 4];
                a[at][3] = qr[8 * QS_PITCH + tg + 4];
            }
            #pragma unroll
            for (int nt = 0; nt < 8; nt++) {
                const float* kr = Ks + (nt * 8 + g) * KS_PITCH + ks * 8;
                float b0 = kr[tg];
                float b1 = kr[tg + 4];
                mma_tf32(sacc[0][nt], a[0][0], a[0][1], a[0][2], a[0][3], b0, b1);
                mma_tf32(sacc[1][nt], a[1][0], a[1][1], a[1][2], a[1][3], b0, b1);
            }
        }

        // ---- mask add / special overwrite ----
        if (qsp && kbase >= S_LEN - 128) {
            #pragma unroll
            for (int at = 0; at < 2; at++)
                #pragma unroll
                for (int nt = 0; nt < 8; nt++)
                    #pragma unroll
                    for (int j = 0; j < 4; j++) {
                        int qg = qbase + wrow + at * 16 + g + (j >> 1) * 8;
                        int kg = kbase + nt * 8 + 2 * tg + (j & 1);
                        sacc[at][nt][j] = (kg <= qg) ? 0.0f : NEG_BIG;
                    }
        } else {
            #pragma unroll
            for (int nt = 0; nt < 8; nt++) {
                float2 mv = *(const float2*)(mk + nt * 8 + 2 * tg);
                #pragma unroll
                for (int at = 0; at < 2; at++) {
                    sacc[at][nt][0] += mv.x;
                    sacc[at][nt][1] += mv.y;
                    sacc[at][nt][2] += mv.x;
                    sacc[at][nt][3] += mv.y;
                }
            }
        }

        // ---- online softmax; p stored back in sacc as tf32 ----
        #pragma unroll
        for (int at = 0; at < 2; at++) {
            #pragma unroll
            for (int rh = 0; rh < 2; rh++) {
                float tm = NEG_BIG;
                #pragma unroll
                for (int nt = 0; nt < 8; nt++) {
                    tm = fmaxf(tm, sacc[at][nt][2 * rh]);
                    tm = fmaxf(tm, sacc[at][nt][2 * rh + 1]);
                }
                tm = fmaxf(tm, __shfl_xor_sync(0xffffffffu, tm, 1));
                tm = fmaxf(tm, __shfl_xor_sync(0xffffffffu, tm, 2));
                float mn = fmaxf(m_st[at][rh], tm);
                float corr = ex2(m_st[at][rh] - mn);
                m_st[at][rh] = mn;
                float ls = 0.0f;
                #pragma unroll
                for (int nt = 0; nt < 8; nt++) {
                    float p0 = ex2(sacc[at][nt][2 * rh] - mn);
                    float p1 = ex2(sacc[at][nt][2 * rh + 1] - mn);
                    ls += p0 + p1;
                    sacc[at][nt][2 * rh]     = f2tf(p0);
                    sacc[at][nt][2 * rh + 1] = f2tf(p1);
                }
                ls += __shfl_xor_sync(0xffffffffu, ls, 1);
                ls += __shfl_xor_sync(0xffffffffu, ls, 2);
                l_st[at][rh] = l_st[at][rh] * corr + ls;
                #pragma unroll
                for (int nt = 0; nt < 8; nt++) {
                    oacc[at][nt][2 * rh] *= corr;
                    oacc[at][nt][2 * rh + 1] *= corr;
                }
            }
        }

        // ---- O += P @ V : a-frags via quad shuffle from sacc c-layout ----
        #pragma unroll
        for (int ks = 0; ks < 8; ks++) {
            float a[2][4];
            #pragma unroll
            for (int at = 0; at < 2; at++) {
                // holder lane qbl has cols {2(tg>>1), 2(tg>>1)+1}; qbl+2 -> +4 cols
                float s0 = __shfl_sync(0xffffffffu, sacc[at][ks][0], qbl);
                float s1 = __shfl_sync(0xffffffffu, sacc[at][ks][1], qbl);
                float s2 = __shfl_sync(0xffffffffu, sacc[at][ks][2], qbl);
                float s3 = __shfl_sync(0xffffffffu, sacc[at][ks][3], qbl);
                float t0 = __shfl_sync(0xffffffffu, sacc[at][ks][0], qbl + 2);
                float t1 = __shfl_sync(0xffffffffu, sacc[at][ks][1], qbl + 2);
                float t2 = __shfl_sync(0xffffffffu, sacc[at][ks][2], qbl + 2);
                float t3 = __shfl_sync(0xffffffffu, sacc[at][ks][3], qbl + 2);
                a[at][0] = podd ? s1 : s0;   // row g,   k = tg
                a[at][1] = podd ? s3 : s2;   // row g+8, k = tg
                a[at][2] = podd ? t1 : t0;   // row g,   k = tg+4
                a[at][3] = podd ? t3 : t2;   // row g+8, k = tg+4
            }
            #pragma unroll
            for (int nt = 0; nt < 8; nt++) {
                const float* vr = Vs + (ks * 8 + tg) * VS_PITCH + nt * 8 + g;
                float b0 = vr[0];
                float b1 = vr[4 * VS_PITCH];
                mma_tf32(oacc[0][nt], a[0][0], a[0][1], a[0][2], a[0][3], b0, b1);
                mma_tf32(oacc[1][nt], a[1][0], a[1][1], a[1][2], a[1][3], b0, b1);
            }
        }
    }

    // ---- epilogue ----
    #pragma unroll
    for (int at = 0; at < 2; at++) {
        #pragma unroll
        for (int rh = 0; rh < 2; rh++) {
            float inv = 1.0f / l_st[at][rh];
            size_t row = (size_t)(qbase + wrow + at * 16 + g + 8 * rh);
            #pragma unroll
            for (int nt = 0; nt < 8; nt++) {
                float2 ov = make_float2(oacc[at][nt][2 * rh] * inv,
                                        oacc[at][nt][2 * rh + 1] * inv);
                *(float2*)(Op + row * DH + nt * 8 + 2 * tg) = ov;
            }
        }
    }
}

extern "C" void kernel_launch(void* const* d_in, const int* in_sizes, int n_in,
                              void* d_out, int out_size)
{
    (void)in_sizes; (void)n_in; (void)out_size;
    const float* Q    = (const float*)d_in[0];
    const float* K    = (const float*)d_in[1];
    const float* V    = (const float*)d_in[2];
    const float* mask = (const float*)d_in[3];
    float* O = (float*)d_out;

    cudaFuncSetAttribute(attn_tf32_kernel,
                         cudaFuncAttributeMaxDynamicSharedMemorySize, SMEM_BYTES);

    dim3 grid(S_LEN / BM, NB * NH);
    attn_tf32_kernel<<<grid, 128, SMEM_BYTES>>>(Q, K, V, mask, O);
}